// round 5
// baseline (speedup 1.0000x reference)
#include <cuda_runtime.h>
#include <cuda_fp16.h>

#define NWALK 8192
#define N_B   128
#define N_W   64
#define SCALE 0.08838834764831845f

// ---------------- device global scratch ----------------
__device__ float g_y[2 * NWALK * 128];
__device__ float g_Wvl[128 * 128];
__device__ float g_bvl[128];
__device__ __align__(16) __half g_wt_hi[2][128 * 128];  // [mat][n][k], mat0=Wq^T
__device__ __align__(16) __half g_wt_lo[2][128 * 128];

// ---------------- walk kernel smem offsets (bytes) ----------------
#define OFF_AHI   0         // half [128][128] swizzled rows of 256B
#define OFF_ALO   32768
#define OFF_WQHI  65536
#define OFF_WQLO  98304
#define OFF_QS    65536     // f32 [128][132] aliases Wq after Q-MMA
#define OFF_WKHI  133120
#define OFF_WKLO  165888
#define OFF_KT    133120    // f32 [128][132] aliases Wk after K-MMA
#define OFF_SCOL  200704    // f32[128]
#define OFF_PART  201216    // f32[16][32]
#define OFF_BQ    203264    // f32[128]
#define OFF_BK    203776    // f32[128]
#define OFF_SGN   204288    // int[64]
#define K1_SMEM   204544

__device__ __forceinline__ unsigned smem_u32(const void* p) {
    unsigned r;
    asm("{ .reg .u64 t; cvta.to.shared.u64 t, %1; cvt.u32.u64 %0, t; }" : "=r"(r) : "l"(p));
    return r;
}
__device__ __forceinline__ void ldsm4(unsigned a, unsigned& r0, unsigned& r1,
                                      unsigned& r2, unsigned& r3) {
    asm volatile("ldmatrix.sync.aligned.m8n8.x4.shared.b16 {%0,%1,%2,%3}, [%4];"
                 : "=r"(r0), "=r"(r1), "=r"(r2), "=r"(r3) : "r"(a));
}
__device__ __forceinline__ void mma16816(float (&c)[4], unsigned a0, unsigned a1,
                                         unsigned a2, unsigned a3, unsigned b0, unsigned b1) {
    asm volatile("mma.sync.aligned.m16n8k16.row.col.f32.f16.f16.f32 "
                 "{%0,%1,%2,%3}, {%4,%5,%6,%7}, {%8,%9}, {%0,%1,%2,%3};"
                 : "+f"(c[0]), "+f"(c[1]), "+f"(c[2]), "+f"(c[3])
                 : "r"(a0), "r"(a1), "r"(a2), "r"(a3), "r"(b0), "r"(b1));
}

// hi/lo 3-split 128x64x128 MMA block per warp: acc[t][..] over n = n0base + 8t
__device__ __forceinline__ void mma_qk(unsigned sbase, int aHi, int aLo, int bHi, int bLo,
                                       int m0, int n0base, int lane, float (&acc)[8][4]) {
    const int rlow = (lane & 7) + ((lane >> 3) & 1) * 8;
    const int sub  = lane >> 4;
#pragma unroll
    for (int split = 0; split < 3; ++split) {
        const int aOff = (split == 2) ? aLo : aHi;
        const int bOff = (split == 1) ? bLo : bHi;
#pragma unroll
        for (int ks = 0; ks < 8; ++ks) {
            const int chunk = 2 * ks + sub;
            const int arow = m0 + rlow;
            unsigned a0, a1, a2, a3;
            ldsm4(sbase + aOff + arow * 256 + (((chunk) ^ (arow & 7)) << 4), a0, a1, a2, a3);
#pragma unroll
            for (int nt = 0; nt < 4; ++nt) {
                const int nrow = n0base + 16 * nt + rlow;
                unsigned b0, b1, b2, b3;
                ldsm4(sbase + bOff + nrow * 256 + (((chunk) ^ (nrow & 7)) << 4), b0, b1, b2, b3);
                mma16816(acc[2 * nt],     a0, a1, a2, a3, b0, b2);
                mma16816(acc[2 * nt + 1], a0, a1, a2, a3, b1, b3);
            }
        }
    }
}

// ---------------------------------------------------------------------------
// Kernel 0: Wvl fold + Wq/Wk transpose + fp16 split
// ---------------------------------------------------------------------------
__global__ void prep_kernel(const float* __restrict__ Wv, const float* __restrict__ bv,
                            const float* __restrict__ Wl, const float* __restrict__ bl,
                            const float* __restrict__ Wq, const float* __restrict__ Wk) {
    __shared__ float part[4][128];
    const int c = threadIdx.x & 127;
    const int s = threadIdx.x >> 7;
    const int j0 = s * 32;
    float acc = 0.f;
    if (blockIdx.x < 128) {
#pragma unroll 8
        for (int j = 0; j < 32; ++j)
            acc += Wv[blockIdx.x * 128 + j0 + j] * Wl[(j0 + j) * 128 + c];
    } else {
#pragma unroll 8
        for (int j = 0; j < 32; ++j) acc += 32.0f * bv[j0 + j] * Wl[(j0 + j) * 128 + c];
    }
    part[s][c] = acc;
    __syncthreads();
    if (threadIdx.x < 128) {
        float r = part[0][c] + part[1][c] + part[2][c] + part[3][c];
        if (blockIdx.x < 128) g_Wvl[blockIdx.x * 128 + c] = r;
        else                  g_bvl[c] = r + bl[c];
    }
    if (blockIdx.x < 128 && threadIdx.x < 256) {
        int n = blockIdx.x, mat = threadIdx.x >> 7, k = threadIdx.x & 127;
        float v = (mat ? Wk : Wq)[k * 128 + n];
        __half h = __float2half(v);
        g_wt_hi[mat][n * 128 + k] = h;
        g_wt_lo[mat][n * 128 + k] = __float2half(v - __half2float(h));
    }
}

// ---------------------------------------------------------------------------
// Kernel 1: walk attention, 2 walks/block (M = 2 walks x 2 sel x 32 = 128)
// ---------------------------------------------------------------------------
__global__ void __launch_bounds__(512, 1)
walk_kernel(const float* __restrict__ timef, const float* __restrict__ posf,
            const float* __restrict__ negf, const float* __restrict__ wgt,
            const int* __restrict__ sgn,
            const float* __restrict__ bq, const float* __restrict__ bk, int woff) {
    extern __shared__ char smc[];
    const unsigned sbase = smem_u32(smc);
    const int tid = threadIdx.x, lane = tid & 31, wid = tid >> 5;
    const int blk = blockIdx.x + woff;
    int*   ssign = (int*)(smc + OFF_SGN);
    float* scol  = (float*)(smc + OFF_SCOL);
    float* partb = (float*)(smc + OFF_PART);
    float* bqs   = (float*)(smc + OFF_BQ);
    float* bks   = (float*)(smc + OFF_BK);

    if (tid < 128) { bqs[tid] = bq[tid]; bks[tid] = bk[tid]; }
    if (tid < 64)  ssign[tid] = sgn[2 * blk * 32 + tid];
    __syncthreads();

    // ---- phase 0: X -> split halves (swizzled); stage weight halves ----
    const long base2 = (long)2 * blk * 32;
#pragma unroll 4
    for (int i = 0; i < 32; ++i) {
        int idx = tid + i * 512;
        int m = idx >> 7, k = idx & 127;
        int w = m >> 6, s = (m >> 5) & 1, l = m & 31;
        long row = base2 + w * 32 + l;
        float val;
        if (k < 19) {
            bool up = (ssign[w * 32 + l] > 0) == (s == 0);
            val = up ? posf[row * 19 + k] : negf[row * 19 + k];
        } else if (k < 127) {
            val = timef[row * 108 + (k - 19)];
        } else {
            val = wgt[row];
        }
        __half h = __float2half(val);
        __half lo = __float2half(val - __half2float(h));
        int off = m * 256 + ((((k >> 3)) ^ (m & 7)) << 4) + (k & 7) * 2;
        *(__half*)(smc + OFF_AHI + off) = h;
        *(__half*)(smc + OFF_ALO + off) = lo;
    }
    for (int idx = tid; idx < 8192; idx += 512) {
        int arr = idx >> 11, j = idx & 2047, n = j >> 4, cc = j & 15;
        const __half* src = (arr & 1) ? g_wt_lo[arr >> 1] : g_wt_hi[arr >> 1];
        int dof = (arr == 0) ? OFF_WQHI : (arr == 1) ? OFF_WQLO
                : (arr == 2) ? OFF_WKHI : OFF_WKLO;
        uint4 v = *(const uint4*)(src + n * 128 + cc * 8);
        *(uint4*)(smc + dof + n * 256 + ((cc ^ (n & 7)) << 4)) = v;
    }
    __syncthreads();

    const int m0 = (wid >> 1) * 16, n0base = (wid & 1) * 64;
    const int srow = lane >> 2, scl = 2 * (lane & 3);
    float* qS = (float*)(smc + OFF_QS);
    float* kT = (float*)(smc + OFF_KT);

    // ---- Q MMA ----
    {
        float acc[8][4];
#pragma unroll
        for (int t = 0; t < 8; ++t)
#pragma unroll
            for (int i = 0; i < 4; ++i) acc[t][i] = 0.f;
        mma_qk(sbase, OFF_AHI, OFF_ALO, OFF_WQHI, OFF_WQLO, m0, n0base, lane, acc);
        __syncthreads();                       // all Wq reads done
#pragma unroll
        for (int t = 0; t < 8; ++t) {
            int col = n0base + 8 * t + scl, row = m0 + srow;
            float b0 = bqs[col], b1 = bqs[col + 1];
            qS[row * 132 + col]           = (acc[t][0] + b0) * SCALE;
            qS[row * 132 + col + 1]       = (acc[t][1] + b1) * SCALE;
            qS[(row + 8) * 132 + col]     = (acc[t][2] + b0) * SCALE;
            qS[(row + 8) * 132 + col + 1] = (acc[t][3] + b1) * SCALE;
        }
    }
    // ---- K MMA (store transposed) ----
    {
        float acc[8][4];
#pragma unroll
        for (int t = 0; t < 8; ++t)
#pragma unroll
            for (int i = 0; i < 4; ++i) acc[t][i] = 0.f;
        mma_qk(sbase, OFF_AHI, OFF_ALO, OFF_WKHI, OFF_WKLO, m0, n0base, lane, acc);
        __syncthreads();                       // all Wk reads done
#pragma unroll
        for (int t = 0; t < 8; ++t) {
            int col = n0base + 8 * t + scl, row = m0 + srow;
            float b0 = bks[col], b1 = bks[col + 1];
            kT[col * 132 + row]           = acc[t][0] + b0;
            kT[(col + 1) * 132 + row]     = acc[t][1] + b1;
            kT[col * 132 + row + 8]       = acc[t][2] + b0;
            kT[(col + 1) * 132 + row + 8] = acc[t][3] + b1;
        }
    }
    __syncthreads();

    // ---- scores + softmax + per-warp colsum (4 groups of 32 rows) ----
    {
        const int v = wid >> 2, rb = (wid & 3) * 8;
        const float* qb = qS + (v * 32 + rb) * 132;
        const float* kb = kT + v * 32 + lane;
        float acc[8];
#pragma unroll
        for (int r = 0; r < 8; ++r) acc[r] = 0.f;
#pragma unroll 4
        for (int c4 = 0; c4 < 32; ++c4) {
            float k0 = kb[(4 * c4 + 0) * 132];
            float k1 = kb[(4 * c4 + 1) * 132];
            float k2 = kb[(4 * c4 + 2) * 132];
            float k3 = kb[(4 * c4 + 3) * 132];
#pragma unroll
            for (int r = 0; r < 8; ++r) {
                const float4 q = *(const float4*)(qb + r * 132 + 4 * c4);
                acc[r] += q.x * k0 + q.y * k1 + q.z * k2 + q.w * k3;
            }
        }
        float csum = 0.f;
#pragma unroll
        for (int r = 0; r < 8; ++r) {
            float x = acc[r];
            float mx = x;
#pragma unroll
            for (int off = 16; off; off >>= 1)
                mx = fmaxf(mx, __shfl_xor_sync(0xffffffffu, mx, off));
            float e = __expf(x - mx);
            float sden = e;
#pragma unroll
            for (int off = 16; off; off >>= 1)
                sden += __shfl_xor_sync(0xffffffffu, sden, off);
            csum += e / sden;
        }
        partb[wid * 32 + lane] = csum;
    }
    __syncthreads();
    if (tid < 128) {
        int v = tid >> 5, mm = tid & 31;
        scol[tid] = partb[(v * 4 + 0) * 32 + mm] + partb[(v * 4 + 1) * 32 + mm] +
                    partb[(v * 4 + 2) * 32 + mm] + partb[(v * 4 + 3) * 32 + mm];
    }
    __syncthreads();

    // ---- phase 4: y = scol^T X  (X = hi + lo) ----
    {
        int v = tid >> 7, k = tid & 127;
        const float* sp = scol + v * 32;
        float acc = 0.f;
#pragma unroll 8
        for (int l = 0; l < 32; ++l) {
            int m = v * 32 + l;
            int off = m * 256 + ((((k >> 3)) ^ (m & 7)) << 4) + (k & 7) * 2;
            float x = __half2float(*(__half*)(smc + OFF_AHI + off)) +
                      __half2float(*(__half*)(smc + OFF_ALO + off));
            acc += sp[l] * x;
        }
        int w = v >> 1, s = v & 1;
        g_y[((long)s * NWALK + 2 * blk + w) * 128 + k] = acc;
    }
}

// ---------------------------------------------------------------------------
// Kernel 2: emb fold + path attention (unchanged from R3)
// ---------------------------------------------------------------------------
#define K2_EMBT  0
#define K2_WVL   (128 * 68)
#define K2_A     (K2_WVL + 128 * 128)
#define K2_Q     K2_A
#define K2_KT    (K2_Q + 64 * 128)
#define K2_SC    (K2_KT + 128 * 65)
#define K2_SCOL  (K2_SC + 64 * 64)
#define K2_YV    (K2_SCOL + 64)
#define K2_SMEM  ((K2_YV + 128) * 4)

__global__ void __launch_bounds__(512, 1)
path_kernel(const float* __restrict__ Wqp, const float* __restrict__ bqp,
            const float* __restrict__ Wkp, const float* __restrict__ bkp,
            const float* __restrict__ Wvp, const float* __restrict__ bvp,
            float* __restrict__ out) {
    extern __shared__ float sm[];
    float* embT = sm + K2_EMBT;
    float* WvlS = sm + K2_WVL;
    float* yT   = sm + K2_A;
    float* q2   = sm + K2_Q;
    float* kT2  = sm + K2_KT;
    float* sc   = sm + K2_SC;
    float* scol = sm + K2_SCOL;
    float* yv   = sm + K2_YV;

    const int tid = threadIdx.x;
    const int sel = blockIdx.x >> 7;
    const int b   = blockIdx.x & 127;
    const float* yg = &g_y[((long)sel * NWALK + b * N_W) * 128];

    for (int idx = tid; idx < N_W * 128; idx += 512) {
        int m = idx >> 7, j = idx & 127;
        yT[j * 68 + m] = yg[idx];
    }
    for (int idx = tid; idx < 128 * 128; idx += 512) WvlS[idx] = g_Wvl[idx];
    __syncthreads();

    {
        const int c = tid & 127;
        const int r0 = (tid >> 7) * 16;
        float acc[16];
#pragma unroll
        for (int i = 0; i < 16; ++i) acc[i] = 0.f;
#pragma unroll 2
        for (int j = 0; j < 128; ++j) {
            float wv = WvlS[j * 128 + c];
            const float4 e0 = *(const float4*)&yT[j * 68 + r0];
            const float4 e1 = *(const float4*)&yT[j * 68 + r0 + 4];
            const float4 e2 = *(const float4*)&yT[j * 68 + r0 + 8];
            const float4 e3 = *(const float4*)&yT[j * 68 + r0 + 12];
            acc[0] += e0.x * wv;  acc[1] += e0.y * wv;  acc[2] += e0.z * wv;  acc[3] += e0.w * wv;
            acc[4] += e1.x * wv;  acc[5] += e1.y * wv;  acc[6] += e1.z * wv;  acc[7] += e1.w * wv;
            acc[8] += e2.x * wv;  acc[9] += e2.y * wv;  acc[10] += e2.z * wv; acc[11] += e2.w * wv;
            acc[12] += e3.x * wv; acc[13] += e3.y * wv; acc[14] += e3.z * wv; acc[15] += e3.w * wv;
        }
        float bias = g_bvl[c];
        __syncthreads();
#pragma unroll
        for (int i = 0; i < 16; ++i) embT[c * 68 + (r0 + i)] = acc[i] + bias;
    }
    __syncthreads();

    {
        const int c = tid & 127;
        const int r0 = (tid >> 7) * 16;
#pragma unroll
        for (int mat = 0; mat < 2; ++mat) {
            const float* W  = mat ? Wkp : Wqp;
            const float* bb = mat ? bkp : bqp;
            float acc[16];
#pragma unroll
            for (int i = 0; i < 16; ++i) acc[i] = 0.f;
#pragma unroll 2
            for (int kk = 0; kk < 128; ++kk) {
                float wv = W[kk * 128 + c];
                const float4 e0 = *(const float4*)&embT[kk * 68 + r0];
                const float4 e1 = *(const float4*)&embT[kk * 68 + r0 + 4];
                const float4 e2 = *(const float4*)&embT[kk * 68 + r0 + 8];
                const float4 e3 = *(const float4*)&embT[kk * 68 + r0 + 12];
                acc[0] += e0.x * wv;  acc[1] += e0.y * wv;  acc[2] += e0.z * wv;  acc[3] += e0.w * wv;
                acc[4] += e1.x * wv;  acc[5] += e1.y * wv;  acc[6] += e1.z * wv;  acc[7] += e1.w * wv;
                acc[8] += e2.x * wv;  acc[9] += e2.y * wv;  acc[10] += e2.z * wv; acc[11] += e2.w * wv;
                acc[12] += e3.x * wv; acc[13] += e3.y * wv; acc[14] += e3.z * wv; acc[15] += e3.w * wv;
            }
            float bias = bb[c];
            if (mat == 0) {
#pragma unroll
                for (int i = 0; i < 16; ++i) q2[(r0 + i) * 128 + c] = acc[i] + bias;
            } else {
#pragma unroll
                for (int i = 0; i < 16; ++i) kT2[c * 65 + (r0 + i)] = acc[i] + bias;
            }
        }
    }
    __syncthreads();

    {
        const int lane = tid & 31;
        const int wid = tid >> 5;
        const int lb = wid * 4;
        const float* q0 = &q2[lb * 128];
        const float* q1 = q0 + 128;
        const float* qq2 = q0 + 256;
        const float* q3 = q0 + 384;
        const float* kbA = &kT2[lane];
        const float* kbB = &kT2[lane + 32];
        float aA[4] = {0.f, 0.f, 0.f, 0.f};
        float aB[4] = {0.f, 0.f, 0.f, 0.f};
#pragma unroll 4
        for (int cc = 0; cc < 128; ++cc) {
            float k0 = kbA[cc * 65];
            float k1 = kbB[cc * 65];
            float v0 = q0[cc], v1 = q1[cc], v2 = qq2[cc], v3 = q3[cc];
            aA[0] += v0 * k0; aB[0] += v0 * k1;
            aA[1] += v1 * k0; aB[1] += v1 * k1;
            aA[2] += v2 * k0; aB[2] += v2 * k1;
            aA[3] += v3 * k0; aB[3] += v3 * k1;
        }
#pragma unroll
        for (int i = 0; i < 4; ++i) {
            float x0 = aA[i] * SCALE, x1 = aB[i] * SCALE;
            float mx = fmaxf(x0, x1);
#pragma unroll
            for (int off = 16; off; off >>= 1)
                mx = fmaxf(mx, __shfl_xor_sync(0xffffffffu, mx, off));
            float e0 = __expf(x0 - mx), e1 = __expf(x1 - mx);
            float sden = e0 + e1;
#pragma unroll
            for (int off = 16; off; off >>= 1)
                sden += __shfl_xor_sync(0xffffffffu, sden, off);
            float inv = 1.f / sden;
            sc[(lb + i) * 64 + lane]      = e0 * inv;
            sc[(lb + i) * 64 + lane + 32] = e1 * inv;
        }
    }
    __syncthreads();

    if (tid < 64) {
        float s = 0.f;
#pragma unroll 4
        for (int l = 0; l < 64; ++l) s += sc[l * 64 + tid];
        scol[tid] = s;
    }
    __syncthreads();
    if (tid < 128) {
        float acc = 0.f;
#pragma unroll 4
        for (int m = 0; m < 64; ++m) acc += scol[m] * embT[tid * 68 + m];
        yv[tid] = acc;
    }
    __syncthreads();
    if (tid < 128) {
        float acc = 64.0f * bvp[tid];
#pragma unroll 4
        for (int k = 0; k < 128; ++k) acc += yv[k] * Wvp[k * 128 + tid];
        out[sel * (N_B * 128) + b * 128 + tid] = acc;
    }
}

// ---------------------------------------------------------------------------
extern "C" void kernel_launch(void* const* d_in, const int* in_sizes, int n_in,
                              void* d_out, int out_size) {
    const float* timef = (const float*)d_in[0];
    const float* posf  = (const float*)d_in[1];
    const float* negf  = (const float*)d_in[2];
    const float* wgt   = (const float*)d_in[3];
    const int*   sgn   = (const int*)  d_in[4];
    const float* Wq    = (const float*)d_in[5];
    const float* bq    = (const float*)d_in[6];
    const float* Wk    = (const float*)d_in[7];
    const float* bk    = (const float*)d_in[8];
    const float* Wv    = (const float*)d_in[9];
    const float* bv    = (const float*)d_in[10];
    const float* Wl    = (const float*)d_in[11];
    const float* bl    = (const float*)d_in[12];
    const float* Wqp   = (const float*)d_in[13];
    const float* bqp   = (const float*)d_in[14];
    const float* Wkp   = (const float*)d_in[15];
    const float* bkp   = (const float*)d_in[16];
    const float* Wvp   = (const float*)d_in[17];
    const float* bvp   = (const float*)d_in[18];

    cudaFuncSetAttribute(walk_kernel, cudaFuncAttributeMaxDynamicSharedMemorySize, K1_SMEM);
    cudaFuncSetAttribute(path_kernel, cudaFuncAttributeMaxDynamicSharedMemorySize, K2_SMEM);

    prep_kernel<<<129, 512>>>(Wv, bv, Wl, bl, Wq, Wk);
    // 4096 blocks total (2 walks each), chunked so ncu lands on a walk launch
    walk_kernel<<<1024, 512, K1_SMEM>>>(timef, posf, negf, wgt, sgn, bq, bk, 0);
    walk_kernel<<<1024, 512, K1_SMEM>>>(timef, posf, negf, wgt, sgn, bq, bk, 1024);
    walk_kernel<<<1024, 512, K1_SMEM>>>(timef, posf, negf, wgt, sgn, bq, bk, 2048);
    walk_kernel<<<1024, 512, K1_SMEM>>>(timef, posf, negf, wgt, sgn, bq, bk, 3072);
    path_kernel<<<256, 512, K2_SMEM>>>(Wqp, bqp, Wkp, bkp, Wvp, bvp, (float*)d_out);
}

// round 6
// speedup vs baseline: 1.4256x; 1.4256x over previous
#include <cuda_runtime.h>
#include <cuda_fp16.h>

#define NWALK 8192
#define N_B   128
#define N_W   64
#define SCALE 0.08838834764831845f

// ---------------- device global scratch ----------------
__device__ float g_y[2 * NWALK * 128];
__device__ float g_Wvl[128 * 128];
__device__ float g_bvl[128];
__device__ float g_gx[128];                      // SCALE * Wk @ bq
__device__ __align__(16) __half g_Gt_hi[128 * 128];  // (SCALE*Wq@Wk^T)^T [n][k]
__device__ __align__(16) __half g_Gt_lo[128 * 128];

// ---------------- walk kernel smem offsets (bytes) ----------------
#define OFF_AHI   0          // half [64][128] swizzled rows 256B (16384)
#define OFF_ALO   16384      // -> 32768
#define OFF_GHI   32768      // half [128][128] swizzled (32768) -> 65536
#define OFF_GLO   65536      // -> 98304
#define OFF_Z     32768      // f32 [64][132] = 33792, aliases GHI after MMA
#define OFF_XT    66560      // f32 [128][66] = 33792, aliases GLO after MMA
#define OFF_W     100352     // f32[64]
#define OFF_SCOL  100608     // f32[64]
#define OFF_PART  100864     // f32[16][32] = 2048
#define OFF_SGN   102912     // int[32]
#define OFF_GX    103040     // f32[128]
#define K1_SMEM   103552     // x2 CTAs = 207104 <= 228KB/SM

__device__ __forceinline__ unsigned smem_u32(const void* p) {
    unsigned r;
    asm("{ .reg .u64 t; cvta.to.shared.u64 t, %1; cvt.u32.u64 %0, t; }" : "=r"(r) : "l"(p));
    return r;
}
__device__ __forceinline__ void ldsm4(unsigned a, unsigned& r0, unsigned& r1,
                                      unsigned& r2, unsigned& r3) {
    asm volatile("ldmatrix.sync.aligned.m8n8.x4.shared.b16 {%0,%1,%2,%3}, [%4];"
                 : "=r"(r0), "=r"(r1), "=r"(r2), "=r"(r3) : "r"(a));
}
__device__ __forceinline__ void mma16816(float (&c)[4], unsigned a0, unsigned a1,
                                         unsigned a2, unsigned a3, unsigned b0, unsigned b1) {
    asm volatile("mma.sync.aligned.m16n8k16.row.col.f32.f16.f16.f32 "
                 "{%0,%1,%2,%3}, {%4,%5,%6,%7}, {%8,%9}, {%0,%1,%2,%3};"
                 : "+f"(c[0]), "+f"(c[1]), "+f"(c[2]), "+f"(c[3])
                 : "r"(a0), "r"(a1), "r"(a2), "r"(a3), "r"(b0), "r"(b1));
}

// ---------------------------------------------------------------------------
// Kernel 0: Wvl fold + Gram matrix G = SCALE*Wq@Wk^T (hi/lo) + gx = SCALE*Wk@bq
// ---------------------------------------------------------------------------
__global__ void prep_kernel(const float* __restrict__ Wv, const float* __restrict__ bv,
                            const float* __restrict__ Wl, const float* __restrict__ bl,
                            const float* __restrict__ Wq, const float* __restrict__ Wk,
                            const float* __restrict__ bq) {
    __shared__ float part[4][128];
    const int c = threadIdx.x & 127;
    const int s = threadIdx.x >> 7;
    const int j0 = s * 32;

    // --- Wvl / bvl ---
    {
        float acc = 0.f;
        if (blockIdx.x < 128) {
#pragma unroll 8
            for (int j = 0; j < 32; ++j)
                acc += Wv[blockIdx.x * 128 + j0 + j] * Wl[(j0 + j) * 128 + c];
        } else {
#pragma unroll 8
            for (int j = 0; j < 32; ++j) acc += 32.0f * bv[j0 + j] * Wl[(j0 + j) * 128 + c];
        }
        part[s][c] = acc;
        __syncthreads();
        if (threadIdx.x < 128) {
            float r = part[0][c] + part[1][c] + part[2][c] + part[3][c];
            if (blockIdx.x < 128) g_Wvl[blockIdx.x * 128 + c] = r;
            else                  g_bvl[c] = r + bl[c];
        }
        __syncthreads();
    }

    if (blockIdx.x < 128) {
        // --- Gt row n = blockIdx.x: Gt[n][k] = SCALE * sum_d Wq[k][d]*Wk[n][d] ---
        const int n = blockIdx.x;
        float acc = 0.f;
#pragma unroll 8
        for (int j = 0; j < 32; ++j)
            acc += Wq[c * 128 + j0 + j] * Wk[n * 128 + j0 + j];
        part[s][c] = acc;
        __syncthreads();
        if (threadIdx.x < 128) {
            float v = SCALE * (part[0][c] + part[1][c] + part[2][c] + part[3][c]);
            __half h = __float2half(v);
            g_Gt_hi[n * 128 + c] = h;
            g_Gt_lo[n * 128 + c] = __float2half(v - __half2float(h));
        }
    } else {
        // --- gx[k] = SCALE * sum_d Wk[k][d]*bq[d] ---
        float acc = 0.f;
#pragma unroll 8
        for (int j = 0; j < 32; ++j) acc += Wk[c * 128 + j0 + j] * bq[j0 + j];
        part[s][c] = acc;
        __syncthreads();
        if (threadIdx.x < 128)
            g_gx[c] = SCALE * (part[0][c] + part[1][c] + part[2][c] + part[3][c]);
    }
}

// ---------------------------------------------------------------------------
// Kernel 1: walk attention. 1 walk/block (M = 2 sel x 32 = 64 rows), occ 2.
// ---------------------------------------------------------------------------
__global__ void __launch_bounds__(512, 2)
walk_kernel(const float* __restrict__ timef, const float* __restrict__ posf,
            const float* __restrict__ negf, const float* __restrict__ wgt,
            const int* __restrict__ sgn, int woff) {
    extern __shared__ char smc[];
    const unsigned sbase = smem_u32(smc);
    const int tid = threadIdx.x, lane = tid & 31, wid = tid >> 5;
    const int blk = blockIdx.x + woff;

    int*   ssign = (int*)(smc + OFF_SGN);
    float* sgx   = (float*)(smc + OFF_GX);
    float* Z     = (float*)(smc + OFF_Z);
    float* xT    = (float*)(smc + OFF_XT);
    float* wv    = (float*)(smc + OFF_W);
    float* scol  = (float*)(smc + OFF_SCOL);
    float* partb = (float*)(smc + OFF_PART);

    if (tid < 32)  ssign[tid] = sgn[blk * 32 + tid];
    if (tid >= 128 && tid < 256) sgx[tid - 128] = g_gx[tid - 128];
    __syncthreads();

    // ---- phase 0: X -> hi/lo swizzled halves; stage G hi/lo ----
    const long rbase = (long)blk * 32;
#pragma unroll 4
    for (int i = 0; i < 16; ++i) {
        int idx = tid + i * 512;
        int m = idx >> 7, k = idx & 127;
        int sel = m >> 5, l = m & 31;
        long row = rbase + l;
        float val;
        if (k < 19) {
            bool up = (ssign[l] > 0) == (sel == 0);
            val = up ? posf[row * 19 + k] : negf[row * 19 + k];
        } else if (k < 127) {
            val = timef[row * 108 + (k - 19)];
        } else {
            val = wgt[row];
        }
        __half h = __float2half(val);
        __half lo = __float2half(val - __half2float(h));
        int off = m * 256 + (((k >> 3) ^ (m & 7)) << 4) + (k & 7) * 2;
        *(__half*)(smc + OFF_AHI + off) = h;
        *(__half*)(smc + OFF_ALO + off) = lo;
    }
    for (int idx = tid; idx < 4096; idx += 512) {
        int arr = idx >> 11, j = idx & 2047, n = j >> 4, cc = j & 15;
        const __half* src = arr ? g_Gt_lo : g_Gt_hi;
        int dof = arr ? OFF_GLO : OFF_GHI;
        uint4 v = *(const uint4*)(src + n * 128 + cc * 8);
        *(uint4*)(smc + dof + n * 256 + ((cc ^ (n & 7)) << 4)) = v;
    }
    __syncthreads();

    // ---- phase 1: Z = X @ G  (M=64, N=128, K=128, hi/lo 3-split) ----
    {
        const int m0 = (wid & 3) * 16, n0 = (wid >> 2) * 32;
        const int rlow = (lane & 7) + ((lane >> 3) & 1) * 8;
        const int sub  = lane >> 4;
        float acc[4][4];
#pragma unroll
        for (int t = 0; t < 4; ++t)
#pragma unroll
            for (int i = 0; i < 4; ++i) acc[t][i] = 0.f;
#pragma unroll
        for (int split = 0; split < 3; ++split) {
            const int aOff = (split == 2) ? OFF_ALO : OFF_AHI;
            const int bOff = (split == 1) ? OFF_GLO : OFF_GHI;
#pragma unroll
            for (int ks = 0; ks < 8; ++ks) {
                const int chunk = 2 * ks + sub;
                const int arow = m0 + rlow;
                unsigned a0, a1, a2, a3;
                ldsm4(sbase + aOff + arow * 256 + ((chunk ^ (arow & 7)) << 4), a0, a1, a2, a3);
#pragma unroll
                for (int nt = 0; nt < 2; ++nt) {
                    const int nrow = n0 + 16 * nt + rlow;
                    unsigned b0, b1, b2, b3;
                    ldsm4(sbase + bOff + nrow * 256 + ((chunk ^ (nrow & 7)) << 4),
                          b0, b1, b2, b3);
                    mma16816(acc[2 * nt],     a0, a1, a2, a3, b0, b2);
                    mma16816(acc[2 * nt + 1], a0, a1, a2, a3, b1, b3);
                }
            }
        }
        __syncthreads();                 // all G reads done before Z overwrite
        const int srow = lane >> 2, scl = 2 * (lane & 3);
#pragma unroll
        for (int t = 0; t < 4; ++t) {
            int col = n0 + 8 * t + scl, row = m0 + srow;
            Z[row * 132 + col]           = acc[t][0];
            Z[row * 132 + col + 1]       = acc[t][1];
            Z[(row + 8) * 132 + col]     = acc[t][2];
            Z[(row + 8) * 132 + col + 1] = acc[t][3];
        }
    }
    __syncthreads();

    // ---- phase 2: repack X (fp32) -> xT[kk][j], conflict-free for scores ----
#pragma unroll 4
    for (int i = 0; i < 16; ++i) {
        int idx = tid + i * 512;
        int j = idx >> 7, kk = idx & 127;
        int off = j * 256 + (((kk >> 3) ^ (j & 7)) << 4) + (kk & 7) * 2;
        xT[kk * 66 + j] = __half2float(*(__half*)(smc + OFF_AHI + off)) +
                          __half2float(*(__half*)(smc + OFF_ALO + off));
    }
    __syncthreads();

    // ---- phase 2b: w_j = x_j . gx ----
    if (tid < 64) {
        float acc = 0.f;
#pragma unroll 8
        for (int kk = 0; kk < 128; ++kk) acc += xT[kk * 66 + tid] * sgx[kk];
        wv[tid] = acc;
    }
    __syncthreads();

    // ---- phase 3: scores s_ij = Z_i . x_j + w_j, softmax, colsum partials ----
    {
        const int g = wid >> 3, rb = (wid & 7) * 4;      // 8 warps per group, 4 rows
        const float* qb = Z + (g * 32 + rb) * 132;
        const float* kb = xT + g * 32 + lane;
        const float wj = wv[g * 32 + lane];
        float acc[4] = {wj, wj, wj, wj};
#pragma unroll 4
        for (int c4 = 0; c4 < 32; ++c4) {
            float k0 = kb[(4 * c4 + 0) * 66];
            float k1 = kb[(4 * c4 + 1) * 66];
            float k2 = kb[(4 * c4 + 2) * 66];
            float k3 = kb[(4 * c4 + 3) * 66];
#pragma unroll
            for (int r = 0; r < 4; ++r) {
                const float4 q = *(const float4*)(qb + r * 132 + 4 * c4);
                acc[r] += q.x * k0 + q.y * k1 + q.z * k2 + q.w * k3;
            }
        }
        float csum = 0.f;
#pragma unroll
        for (int r = 0; r < 4; ++r) {
            float x = acc[r];
            float mx = x;
#pragma unroll
            for (int off = 16; off; off >>= 1)
                mx = fmaxf(mx, __shfl_xor_sync(0xffffffffu, mx, off));
            float e = __expf(x - mx);
            float sden = e;
#pragma unroll
            for (int off = 16; off; off >>= 1)
                sden += __shfl_xor_sync(0xffffffffu, sden, off);
            csum += e / sden;
        }
        partb[wid * 32 + lane] = csum;
    }
    __syncthreads();
    if (tid < 64) {
        int g = tid >> 5, j = tid & 31;
        float s = 0.f;
#pragma unroll
        for (int w8 = 0; w8 < 8; ++w8) s += partb[(g * 8 + w8) * 32 + j];
        scol[tid] = s;
    }
    __syncthreads();

    // ---- phase 4: y_g = sum_j scol[g][j] * x_j  ->  g_y ----
    if (tid < 256) {
        int g = tid >> 7, k = tid & 127;
        const float* sp = scol + g * 32;
        const float* xb = xT + k * 66 + g * 32;
        float acc = 0.f;
#pragma unroll 8
        for (int j = 0; j < 32; ++j) acc += sp[j] * xb[j];
        g_y[((long)g * NWALK + blk) * 128 + k] = acc;
    }
}

// ---------------------------------------------------------------------------
// Kernel 2: emb fold + path attention (unchanged)
// ---------------------------------------------------------------------------
#define K2_EMBT  0
#define K2_WVL   (128 * 68)
#define K2_A     (K2_WVL + 128 * 128)
#define K2_Q     K2_A
#define K2_KT    (K2_Q + 64 * 128)
#define K2_SC    (K2_KT + 128 * 65)
#define K2_SCOL  (K2_SC + 64 * 64)
#define K2_YV    (K2_SCOL + 64)
#define K2_SMEM  ((K2_YV + 128) * 4)

__global__ void __launch_bounds__(512, 1)
path_kernel(const float* __restrict__ Wqp, const float* __restrict__ bqp,
            const float* __restrict__ Wkp, const float* __restrict__ bkp,
            const float* __restrict__ Wvp, const float* __restrict__ bvp,
            float* __restrict__ out) {
    extern __shared__ float sm[];
    float* embT = sm + K2_EMBT;
    float* WvlS = sm + K2_WVL;
    float* yT   = sm + K2_A;
    float* q2   = sm + K2_Q;
    float* kT2  = sm + K2_KT;
    float* sc   = sm + K2_SC;
    float* scol = sm + K2_SCOL;
    float* yv   = sm + K2_YV;

    const int tid = threadIdx.x;
    const int sel = blockIdx.x >> 7;
    const int b   = blockIdx.x & 127;
    const float* yg = &g_y[((long)sel * NWALK + b * N_W) * 128];

    for (int idx = tid; idx < N_W * 128; idx += 512) {
        int m = idx >> 7, j = idx & 127;
        yT[j * 68 + m] = yg[idx];
    }
    for (int idx = tid; idx < 128 * 128; idx += 512) WvlS[idx] = g_Wvl[idx];
    __syncthreads();

    {
        const int c = tid & 127;
        const int r0 = (tid >> 7) * 16;
        float acc[16];
#pragma unroll
        for (int i = 0; i < 16; ++i) acc[i] = 0.f;
#pragma unroll 2
        for (int j = 0; j < 128; ++j) {
            float wvv = WvlS[j * 128 + c];
            const float4 e0 = *(const float4*)&yT[j * 68 + r0];
            const float4 e1 = *(const float4*)&yT[j * 68 + r0 + 4];
            const float4 e2 = *(const float4*)&yT[j * 68 + r0 + 8];
            const float4 e3 = *(const float4*)&yT[j * 68 + r0 + 12];
            acc[0] += e0.x * wvv;  acc[1] += e0.y * wvv;  acc[2] += e0.z * wvv;  acc[3] += e0.w * wvv;
            acc[4] += e1.x * wvv;  acc[5] += e1.y * wvv;  acc[6] += e1.z * wvv;  acc[7] += e1.w * wvv;
            acc[8] += e2.x * wvv;  acc[9] += e2.y * wvv;  acc[10] += e2.z * wvv; acc[11] += e2.w * wvv;
            acc[12] += e3.x * wvv; acc[13] += e3.y * wvv; acc[14] += e3.z * wvv; acc[15] += e3.w * wvv;
        }
        float bias = g_bvl[c];
        __syncthreads();
#pragma unroll
        for (int i = 0; i < 16; ++i) embT[c * 68 + (r0 + i)] = acc[i] + bias;
    }
    __syncthreads();

    {
        const int c = tid & 127;
        const int r0 = (tid >> 7) * 16;
#pragma unroll
        for (int mat = 0; mat < 2; ++mat) {
            const float* W  = mat ? Wkp : Wqp;
            const float* bb = mat ? bkp : bqp;
            float acc[16];
#pragma unroll
            for (int i = 0; i < 16; ++i) acc[i] = 0.f;
#pragma unroll 2
            for (int kk = 0; kk < 128; ++kk) {
                float wvv = W[kk * 128 + c];
                const float4 e0 = *(const float4*)&embT[kk * 68 + r0];
                const float4 e1 = *(const float4*)&embT[kk * 68 + r0 + 4];
                const float4 e2 = *(const float4*)&embT[kk * 68 + r0 + 8];
                const float4 e3 = *(const float4*)&embT[kk * 68 + r0 + 12];
                acc[0] += e0.x * wvv;  acc[1] += e0.y * wvv;  acc[2] += e0.z * wvv;  acc[3] += e0.w * wvv;
                acc[4] += e1.x * wvv;  acc[5] += e1.y * wvv;  acc[6] += e1.z * wvv;  acc[7] += e1.w * wvv;
                acc[8] += e2.x * wvv;  acc[9] += e2.y * wvv;  acc[10] += e2.z * wvv; acc[11] += e2.w * wvv;
                acc[12] += e3.x * wvv; acc[13] += e3.y * wvv; acc[14] += e3.z * wvv; acc[15] += e3.w * wvv;
            }
            float bias = bb[c];
            if (mat == 0) {
#pragma unroll
                for (int i = 0; i < 16; ++i) q2[(r0 + i) * 128 + c] = acc[i] + bias;
            } else {
#pragma unroll
                for (int i = 0; i < 16; ++i) kT2[c * 65 + (r0 + i)] = acc[i] + bias;
            }
        }
    }
    __syncthreads();

    {
        const int lane = tid & 31;
        const int wid = tid >> 5;
        const int lb = wid * 4;
        const float* q0 = &q2[lb * 128];
        const float* q1 = q0 + 128;
        const float* qq2 = q0 + 256;
        const float* q3 = q0 + 384;
        const float* kbA = &kT2[lane];
        const float* kbB = &kT2[lane + 32];
        float aA[4] = {0.f, 0.f, 0.f, 0.f};
        float aB[4] = {0.f, 0.f, 0.f, 0.f};
#pragma unroll 4
        for (int cc = 0; cc < 128; ++cc) {
            float k0 = kbA[cc * 65];
            float k1 = kbB[cc * 65];
            float v0 = q0[cc], v1 = q1[cc], v2 = qq2[cc], v3 = q3[cc];
            aA[0] += v0 * k0; aB[0] += v0 * k1;
            aA[1] += v1 * k0; aB[1] += v1 * k1;
            aA[2] += v2 * k0; aB[2] += v2 * k1;
            aA[3] += v3 * k0; aB[3] += v3 * k1;
        }
#pragma unroll
        for (int i = 0; i < 4; ++i) {
            float x0 = aA[i] * SCALE, x1 = aB[i] * SCALE;
            float mx = fmaxf(x0, x1);
#pragma unroll
            for (int off = 16; off; off >>= 1)
                mx = fmaxf(mx, __shfl_xor_sync(0xffffffffu, mx, off));
            float e0 = __expf(x0 - mx), e1 = __expf(x1 - mx);
            float sden = e0 + e1;
#pragma unroll
            for (int off = 16; off; off >>= 1)
                sden += __shfl_xor_sync(0xffffffffu, sden, off);
            float inv = 1.f / sden;
            sc[(lb + i) * 64 + lane]      = e0 * inv;
            sc[(lb + i) * 64 + lane + 32] = e1 * inv;
        }
    }
    __syncthreads();

    if (tid < 64) {
        float s = 0.f;
#pragma unroll 4
        for (int l = 0; l < 64; ++l) s += sc[l * 64 + tid];
        scol[tid] = s;
    }
    __syncthreads();
    if (tid < 128) {
        float acc = 0.f;
#pragma unroll 4
        for (int m = 0; m < 64; ++m) acc += scol[m] * embT[tid * 68 + m];
        yv[tid] = acc;
    }
    __syncthreads();
    if (tid < 128) {
        float acc = 64.0f * bvp[tid];
#pragma unroll 4
        for (int k = 0; k < 128; ++k) acc += yv[k] * Wvp[k * 128 + tid];
        out[sel * (N_B * 128) + b * 128 + tid] = acc;
    }
}

// ---------------------------------------------------------------------------
extern "C" void kernel_launch(void* const* d_in, const int* in_sizes, int n_in,
                              void* d_out, int out_size) {
    const float* timef = (const float*)d_in[0];
    const float* posf  = (const float*)d_in[1];
    const float* negf  = (const float*)d_in[2];
    const float* wgt   = (const float*)d_in[3];
    const int*   sgn   = (const int*)  d_in[4];
    const float* Wq    = (const float*)d_in[5];
    const float* bq    = (const float*)d_in[6];
    const float* Wk    = (const float*)d_in[7];
    const float* Wv    = (const float*)d_in[9];
    const float* bv    = (const float*)d_in[10];
    const float* Wl    = (const float*)d_in[11];
    const float* bl    = (const float*)d_in[12];
    const float* Wqp   = (const float*)d_in[13];
    const float* bqp   = (const float*)d_in[14];
    const float* Wkp   = (const float*)d_in[15];
    const float* bkp   = (const float*)d_in[16];
    const float* Wvp   = (const float*)d_in[17];
    const float* bvp   = (const float*)d_in[18];

    cudaFuncSetAttribute(walk_kernel, cudaFuncAttributeMaxDynamicSharedMemorySize, K1_SMEM);
    cudaFuncSetAttribute(path_kernel, cudaFuncAttributeMaxDynamicSharedMemorySize, K2_SMEM);

    prep_kernel<<<129, 512>>>(Wv, bv, Wl, bl, Wq, Wk, bq);
    // 8192 walks, chunked so ncu (-s 5) lands on a walk launch
    walk_kernel<<<2048, 512, K1_SMEM>>>(timef, posf, negf, wgt, sgn, 0);
    walk_kernel<<<2048, 512, K1_SMEM>>>(timef, posf, negf, wgt, sgn, 2048);
    walk_kernel<<<2048, 512, K1_SMEM>>>(timef, posf, negf, wgt, sgn, 4096);
    walk_kernel<<<2048, 512, K1_SMEM>>>(timef, posf, negf, wgt, sgn, 6144);
    path_kernel<<<256, 512, K2_SMEM>>>(Wqp, bqp, Wkp, bkp, Wvp, bvp, (float*)d_out);
}